// round 12
// baseline (speedup 1.0000x reference)
#include <cuda_runtime.h>
#include <cuda_bf16.h>
#include <cstdint>

// CostVolumeConcat: out (B, 2C, D, H, W) fp32
//   out[b, c,     d, h, w] = (w >= d) ? left [b, c, h, w]     : 0
//   out[b, C + c, d, h, w] = (w >= d) ? right[b, c, h, w - d] : 0
// B=4, C=32, D=48, H=64, W=128.
//
// R12 (= R11 resubmit; R11 hit an infra container failure):
// 256-bit stores (st.global.v8.b32, sm_100a). Each lane emits one 32B store
// per (side, d); half-warps take adjacent d-levels so a warp writes 1KB
// contiguous per side per iter. Right-shift is branch-free via a 48-float
// zero pad ahead of the smem row (w - d < 0 lands in the pad).

#define W_ 128
#define H_ 64
#define C_ 32
#define D_ 48
#define B_ 4
#define ROWF 8192          // floats between d-levels (H*W)
#define PAD_ 48

__device__ __forceinline__ void stg256(float* p, const float* v) {
    asm volatile("st.global.v8.b32 [%0], {%1,%2,%3,%4,%5,%6,%7,%8};"
                 :: "l"(p),
                    "r"(__float_as_uint(v[0])), "r"(__float_as_uint(v[1])),
                    "r"(__float_as_uint(v[2])), "r"(__float_as_uint(v[3])),
                    "r"(__float_as_uint(v[4])), "r"(__float_as_uint(v[5])),
                    "r"(__float_as_uint(v[6])), "r"(__float_as_uint(v[7]))
                 : "memory");
}

__global__ __launch_bounds__(256) void cost_volume_concat_kernel(
    const float* __restrict__ left,
    const float* __restrict__ right,
    float* __restrict__ out)
{
    __shared__ __align__(16) float sL[W_];
    __shared__ __align__(16) float sRp[PAD_ + W_];   // 48-float zero pad + row

    const int h = blockIdx.x;
    const int c = blockIdx.y;
    const int b = blockIdx.z;
    const int t = threadIdx.x;

    const size_t in_off = ((size_t)((b * C_ + c) * H_ + h)) * W_;
    if (t < 32) {
        ((float4*)sL)[t] = ((const float4*)(left + in_off))[t];
    } else if (t < 64) {
        ((float4*)(sRp + PAD_))[t - 32] = ((const float4*)(right + in_off))[t - 32];
    } else if (t < 64 + PAD_) {
        sRp[t - 64] = 0.0f;                 // zero pad
    }
    __syncthreads();

    const int warp = t >> 5;
    const int lane = t & 31;
    const int lh   = lane >> 4;             // half-warp: d offset
    const int w8   = lane & 15;             // float8 index along W
    const int wbase = w8 << 3;              // first w this lane covers

    // left row chunk for this lane (loop-invariant): 2 aligned LDS.128
    float lf[8];
    *(float4*)(lf)     = ((const float4*)sL)[2 * w8];
    *(float4*)(lf + 4) = ((const float4*)sL)[2 * w8 + 1];

    // Output bases (float units). Channels: [0..C)=cost_l, [C..2C)=cost_r.
    float* outL = out + (((size_t)(b * 2 * C_ + c)      * D_) * H_ + h) * W_;
    float* outR = out + (((size_t)(b * 2 * C_ + C_ + c) * D_) * H_ + h) * W_;

    #pragma unroll
    for (int it = 0; it < 3; it++) {
        const int d = 2 * warp + lh + 16 * it;   // covers 0..47 exactly once
        float* pL = outL + (size_t)d * ROWF + wbase;
        float* pR = outR + (size_t)d * ROWF + wbase;

        // ---- left: mask w < d ----
        float v[8];
        #pragma unroll
        for (int j = 0; j < 8; j++)
            v[j] = (wbase + j >= d) ? lf[j] : 0.0f;
        stg256(pL, v);

        // ---- right: shifted read through zero pad (branch-free) ----
        const float* src = sRp + PAD_ + wbase - d;   // index >= 1 always
        float r[8];
        #pragma unroll
        for (int j = 0; j < 8; j++)
            r[j] = src[j];
        stg256(pR, r);
    }
}

extern "C" void kernel_launch(void* const* d_in, const int* in_sizes, int n_in,
                              void* d_out, int out_size)
{
    const float* left  = (const float*)d_in[0];
    const float* right = (const float*)d_in[1];
    float* out = (float*)d_out;

    dim3 grid(H_, C_, B_);   // (64, 32, 4) = 8192 CTAs
    cost_volume_concat_kernel<<<grid, 256>>>(left, right, out);
}

// round 13
// speedup vs baseline: 1.1234x; 1.1234x over previous
#include <cuda_runtime.h>
#include <cuda_bf16.h>

// CostVolumeConcat: out (B, 2C, D, H, W) fp32
//   out[b, c,     d, h, w] = (w >= d) ? left [b, c, h, w]     : 0
//   out[b, C + c, d, h, w] = (w >= d) ? right[b, c, h, w - d] : 0
// B=4, C=32, D=48, H=64, W=128.
//
// FINAL (= R3, best-measured variant). Store-bound kernel at the chip's
// pure-write HBM floor (~5.4 TB/s): six structurally different variants
// (granule size, CTA count, store width 128/256-bit, cache policies) all
// measure 64-66us in ncu with DRAM pinned at ~66%. Structure: one CTA per
// (b,c,h) row; warp-uniform d; left row value hoisted to one LDS.128; right
// shift via two conflict-free LDS.128 + register permute (dr = warp&3 is
// loop-invariant); evict-first streaming stores.

#define W_ 128
#define H_ 64
#define C_ 32
#define D_ 48
#define B_ 4
#define DSTR4 ((H_ * W_) / 4)   // float4 stride between d-levels = 2048

__global__ __launch_bounds__(256) void cost_volume_concat_kernel(
    const float* __restrict__ left,
    const float* __restrict__ right,
    float* __restrict__ out)
{
    __shared__ float4 sL[W_ / 4];
    __shared__ float4 sR[W_ / 4];

    const int h = blockIdx.x;
    const int c = blockIdx.y;
    const int b = blockIdx.z;
    const int t = threadIdx.x;

    const size_t in_off = ((size_t)((b * C_ + c) * H_ + h)) * W_;
    if (t < 32) {
        sL[t] = ((const float4*)(left + in_off))[t];
    } else if (t < 64) {
        sR[t - 32] = ((const float4*)(right + in_off))[t - 32];
    }
    __syncthreads();

    const int warp = t >> 5;
    const int w4   = t & 31;
    const int w0   = w4 << 2;

    // Output bases (float4 units). Channels: [0..C) = cost_l, [C..2C) = cost_r.
    float4* pL = (float4*)out + ((((size_t)(b * 2 * C_ + c)      * D_ + warp) * H_ + h) * W_) / 4 + w4;
    float4* pR = (float4*)out + ((((size_t)(b * 2 * C_ + C_ + c) * D_ + warp) * H_ + h) * W_) / 4 + w4;

    // ---- left: row value is loop-invariant (one LDS.128 total) ----
    const float4 vbase = sL[w4];
    #pragma unroll
    for (int it = 0; it < 6; it++) {
        const int d = warp + 8 * it;
        float4 v = vbase;
        if (w0 < d) {                       // boundary warps only
            v.x = (w0     >= d) ? v.x : 0.0f;
            v.y = (w0 + 1 >= d) ? v.y : 0.0f;
            v.z = (w0 + 2 >= d) ? v.z : 0.0f;
            v.w = (w0 + 3 >= d) ? v.w : 0.0f;
        }
        __stcs(pL, v);
        pL += 8 * DSTR4;
    }

    // ---- right: shifted row. d = warp + 8*it, dr = d&3 = warp&3 (invariant),
    //      dq = d>>2 = (warp>>2) + 2*it. Element j of lane w4 reads
    //      sR_flat[4*w4 - d + j]; OOB float4 -> zero reproduces the w<d mask.
    const int dr = warp & 3;
    int ib = w4 - (warp >> 2);              // block index at it=0; -2 per iter
    const float4 z4 = make_float4(0.f, 0.f, 0.f, 0.f);

    if (dr == 0) {
        #pragma unroll
        for (int it = 0; it < 6; it++) {
            float4 v = (ib >= 0) ? sR[ib] : z4;
            __stcs(pR, v);
            pR += 8 * DSTR4;  ib -= 2;
        }
    } else if (dr == 1) {
        #pragma unroll
        for (int it = 0; it < 6; it++) {
            float4 Bv = (ib     >= 0) ? sR[ib]     : z4;
            float4 Av = (ib - 1 >= 0) ? sR[ib - 1] : z4;
            __stcs(pR, make_float4(Av.w, Bv.x, Bv.y, Bv.z));
            pR += 8 * DSTR4;  ib -= 2;
        }
    } else if (dr == 2) {
        #pragma unroll
        for (int it = 0; it < 6; it++) {
            float4 Bv = (ib     >= 0) ? sR[ib]     : z4;
            float4 Av = (ib - 1 >= 0) ? sR[ib - 1] : z4;
            __stcs(pR, make_float4(Av.z, Av.w, Bv.x, Bv.y));
            pR += 8 * DSTR4;  ib -= 2;
        }
    } else {
        #pragma unroll
        for (int it = 0; it < 6; it++) {
            float4 Bv = (ib     >= 0) ? sR[ib]     : z4;
            float4 Av = (ib - 1 >= 0) ? sR[ib - 1] : z4;
            __stcs(pR, make_float4(Av.y, Av.z, Av.w, Bv.x));
            pR += 8 * DSTR4;  ib -= 2;
        }
    }
}

extern "C" void kernel_launch(void* const* d_in, const int* in_sizes, int n_in,
                              void* d_out, int out_size)
{
    const float* left  = (const float*)d_in[0];
    const float* right = (const float*)d_in[1];
    float* out = (float*)d_out;

    dim3 grid(H_, C_, B_);   // (64, 32, 4) = 8192 CTAs
    cost_volume_concat_kernel<<<grid, 256>>>(left, right, out);
}